// round 1
// baseline (speedup 1.0000x reference)
#include <cuda_runtime.h>
#include <math.h>

// ---------------------------------------------------------------------------
// Problem constants
// ---------------------------------------------------------------------------
#define NBATCH 8
#define NCH    64
#define MAPH   96
#define NBR    8           // 2 * NUM_ANCHOR branches
#define BSTR   104         // buffer row stride (max intermediate extent)
#define BCHS   (BSTR*BSTR) // 10816, per-channel stride in buffers
#define WSET   (64*9*64)   // 36864 floats per weight set [ic][tap][oc]

// ---------------------------------------------------------------------------
// Device-global scratch (static allocation: no cudaMalloc allowed)
// ---------------------------------------------------------------------------
__device__ float g_buf1[(size_t)NBR*NBATCH*NCH*BCHS]; // stage1 outputs (96 or 104 valid, stride 104)
__device__ float g_buf2[(size_t)NBR*NBATCH*NCH*BCHS]; // stage2 outputs (96 or 100 valid, stride 104)
__device__ float g_bmax[NBR*NBATCH*MAPH*MAPH];        // per-branch channel-max
__device__ float g_w1[NBR*WSET];                      // stage1: perm+rot+BN folded, per branch
__device__ float g_w2[4*WSET];                        // stage2: rot+BN folded, per rotation k
__device__ float g_w3[4*WSET];                        // stage3
__device__ float g_bias[3*64];                        // folded bias per stage

// rot90(W, -k) source index for kernel tap (A,B)
__device__ __forceinline__ void rotmap(int k, int A, int B, int& sa, int& sb) {
    switch (k & 3) {
        case 0: sa = A;     sb = B;     break;
        case 1: sa = 2 - B; sb = A;     break;
        case 2: sa = 2 - A; sb = 2 - B; break;
        default: sa = B;    sb = 2 - A; break;
    }
}

// ---------------------------------------------------------------------------
// Weight / bias preparation: fold BN scale, rotate kernels, permute stage-1
// input channels. ~590k elements, negligible cost.
// ---------------------------------------------------------------------------
__global__ void prep_kernel(
    const float* __restrict__ dcn_w, const float* __restrict__ dcn_b,
    const float* __restrict__ c2w,   const float* __restrict__ c2b,
    const float* __restrict__ c3w,   const float* __restrict__ c3b,
    const float* __restrict__ gam,   const float* __restrict__ bet,
    const float* __restrict__ mu,    const float* __restrict__ va)
{
    const int W1N = NBR * WSET;      // 294912
    const int W2N = 4 * WSET;        // 147456
    int id = blockIdx.x * blockDim.x + threadIdx.x;

    if (id < W1N) {
        int oc  = id & 63;
        int tap = (id >> 6) % 9;
        int ic  = (id / 576) & 63;
        int br  = id / WSET;
        int sa, sb; rotmap(br & 3, tap / 3, tap % 3, sa, sb);
        int sc = (ic + 8 * br) & 63;                 // channel-roll permutation
        float scale = gam[oc] * rsqrtf(va[oc] + 1e-5f);
        g_w1[id] = dcn_w[((oc * 64 + sc) * 3 + sa) * 3 + sb] * scale;
        return;
    }
    id -= W1N;
    if (id < W2N) {
        int oc  = id & 63;
        int tap = (id >> 6) % 9;
        int ic  = (id / 576) & 63;
        int k   = id / WSET;
        int sa, sb; rotmap(k, tap / 3, tap % 3, sa, sb);
        float scale = gam[64 + oc] * rsqrtf(va[64 + oc] + 1e-5f);
        g_w2[id] = c2w[((oc * 64 + ic) * 3 + sa) * 3 + sb] * scale;
        return;
    }
    id -= W2N;
    if (id < W2N) {
        int oc  = id & 63;
        int tap = (id >> 6) % 9;
        int ic  = (id / 576) & 63;
        int k   = id / WSET;
        int sa, sb; rotmap(k, tap / 3, tap % 3, sa, sb);
        float scale = gam[128 + oc] * rsqrtf(va[128 + oc] + 1e-5f);
        g_w3[id] = c3w[((oc * 64 + ic) * 3 + sa) * 3 + sb] * scale;
        return;
    }
    id -= W2N;
    if (id < 192) {
        int s = id / 64, oc = id & 63;
        float scale = gam[s * 64 + oc] * rsqrtf(va[s * 64 + oc] + 1e-5f);
        const float* cb = (s == 0) ? dcn_b : ((s == 1) ? c2b : c3b);
        g_bias[id] = cb[oc] * scale + bet[s * 64 + oc] - mu[s * 64 + oc] * scale;
    }
}

// ---------------------------------------------------------------------------
// Direct conv, smem-tiled. Block = 128 threads (tx 0..15 = pixel column,
// ty 0..7 = group of 8 output channels). Block tile: 64 oc x (16w x 4h).
// K loop over 64 input channels in chunks of 8.
// ---------------------------------------------------------------------------
template<int D, int STAGE>
__global__ void __launch_bounds__(128)
conv_mid_k(const float* __restrict__ x, int inValid, int outH, int outW,
           int pad, int branch0)
{
    constexpr int RH = 4 + 2 * D;
    constexpr int RW = 16 + 2 * D;
    constexpr int INSTRIDE = (STAGE == 1) ? MAPH : BSTR;
    constexpr int CHS = INSTRIDE * INSTRIDE;

    __shared__ float s_in[8][RH][RW];
    __shared__ float s_w[8][9][64];

    const int tid = threadIdx.x;
    const int tx = tid & 15;
    const int ty = tid >> 4;
    const int z = blockIdx.z;
    const int br = branch0 + 2 * (z >> 3);
    const int b = z & 7;

    const float* inp = (STAGE == 1)
        ? (x + (size_t)b * NCH * CHS)
        : (g_buf1 + (size_t)(br * NBATCH + b) * NCH * BCHS);
    const float* wts = (STAGE == 1)
        ? (g_w1 + br * WSET)
        : (g_w2 + (br & 3) * WSET);
    const float* bias = g_bias + (STAGE - 1) * 64;
    float* outp = ((STAGE == 1) ? g_buf1 : g_buf2)
                  + (size_t)(br * NBATCH + b) * NCH * BCHS;

    const int rowBase = blockIdx.y * 4;
    const int colBase = blockIdx.x * 16;

    float acc[8][4];
    #pragma unroll
    for (int o = 0; o < 8; o++)
        #pragma unroll
        for (int r = 0; r < 4; r++) acc[o][r] = 0.f;

    for (int ic0 = 0; ic0 < 64; ic0 += 8) {
        // weights: 8 ic x 9 taps x 64 oc, contiguous in global
        const float* wsrc = wts + ic0 * 576;
        float* swf = &s_w[0][0][0];
        for (int i = tid; i < 4608; i += 128) swf[i] = wsrc[i];

        // input patch: 8 ic x RH x RW with implicit zero padding
        constexpr int NIN = 8 * RH * RW;
        for (int i = tid; i < NIN; i += 128) {
            int ic = i / (RH * RW);
            int rem = i - ic * (RH * RW);
            int r = rem / RW;
            int c = rem - r * RW;
            int gy = rowBase + r - pad;
            int gx = colBase + c - pad;
            float v = 0.f;
            if ((unsigned)gy < (unsigned)inValid && (unsigned)gx < (unsigned)inValid)
                v = inp[(ic0 + ic) * CHS + gy * INSTRIDE + gx];
            s_in[ic][r][c] = v;
        }
        __syncthreads();

        #pragma unroll 1
        for (int ic = 0; ic < 8; ic++) {
            #pragma unroll
            for (int ky = 0; ky < 3; ky++) {
                #pragma unroll
                for (int kx = 0; kx < 3; kx++) {
                    const float4 wlo = *reinterpret_cast<const float4*>(&s_w[ic][ky * 3 + kx][ty * 8]);
                    const float4 whi = *reinterpret_cast<const float4*>(&s_w[ic][ky * 3 + kx][ty * 8 + 4]);
                    const float i0 = s_in[ic][ky * D + 0][tx + kx * D];
                    const float i1 = s_in[ic][ky * D + 1][tx + kx * D];
                    const float i2 = s_in[ic][ky * D + 2][tx + kx * D];
                    const float i3 = s_in[ic][ky * D + 3][tx + kx * D];
                    float w8[8] = {wlo.x, wlo.y, wlo.z, wlo.w, whi.x, whi.y, whi.z, whi.w};
                    #pragma unroll
                    for (int o = 0; o < 8; o++) {
                        acc[o][0] += w8[o] * i0;
                        acc[o][1] += w8[o] * i1;
                        acc[o][2] += w8[o] * i2;
                        acc[o][3] += w8[o] * i3;
                    }
                }
            }
        }
        __syncthreads();
    }

    float bl[8];
    #pragma unroll
    for (int o = 0; o < 8; o++) bl[o] = bias[ty * 8 + o];

    #pragma unroll
    for (int o = 0; o < 8; o++) {
        const int oc = ty * 8 + o;
        #pragma unroll
        for (int r = 0; r < 4; r++) {
            int oy = rowBase + r, ox = colBase + tx;
            if (oy < outH && ox < outW)
                outp[oc * BCHS + oy * BSTR + ox] = fmaxf(acc[o][r] + bl[o], 0.f);
        }
    }
}

// Stage 3: same conv, but fuse ReLU + max over the 64 output channels; write
// per-branch channel max. D = 2 always.
__global__ void __launch_bounds__(128)
conv_last_k(int inValid, int pad, int branch0)
{
    constexpr int D = 2;
    constexpr int RH = 4 + 2 * D;
    constexpr int RW = 16 + 2 * D;

    __shared__ float s_in[8][RH][RW];
    __shared__ float s_w[8][9][64];
    __shared__ float s_red[8][64];

    const int tid = threadIdx.x;
    const int tx = tid & 15;
    const int ty = tid >> 4;
    const int z = blockIdx.z;
    const int br = branch0 + 2 * (z >> 3);
    const int b = z & 7;

    const float* inp = g_buf2 + (size_t)(br * NBATCH + b) * NCH * BCHS;
    const float* wts = g_w3 + (br & 3) * WSET;
    const float* bias = g_bias + 128;

    const int rowBase = blockIdx.y * 4;
    const int colBase = blockIdx.x * 16;

    float acc[8][4];
    #pragma unroll
    for (int o = 0; o < 8; o++)
        #pragma unroll
        for (int r = 0; r < 4; r++) acc[o][r] = 0.f;

    for (int ic0 = 0; ic0 < 64; ic0 += 8) {
        const float* wsrc = wts + ic0 * 576;
        float* swf = &s_w[0][0][0];
        for (int i = tid; i < 4608; i += 128) swf[i] = wsrc[i];

        constexpr int NIN = 8 * RH * RW;
        for (int i = tid; i < NIN; i += 128) {
            int ic = i / (RH * RW);
            int rem = i - ic * (RH * RW);
            int r = rem / RW;
            int c = rem - r * RW;
            int gy = rowBase + r - pad;
            int gx = colBase + c - pad;
            float v = 0.f;
            if ((unsigned)gy < (unsigned)inValid && (unsigned)gx < (unsigned)inValid)
                v = inp[(ic0 + ic) * BCHS + gy * BSTR + gx];
            s_in[ic][r][c] = v;
        }
        __syncthreads();

        #pragma unroll 1
        for (int ic = 0; ic < 8; ic++) {
            #pragma unroll
            for (int ky = 0; ky < 3; ky++) {
                #pragma unroll
                for (int kx = 0; kx < 3; kx++) {
                    const float4 wlo = *reinterpret_cast<const float4*>(&s_w[ic][ky * 3 + kx][ty * 8]);
                    const float4 whi = *reinterpret_cast<const float4*>(&s_w[ic][ky * 3 + kx][ty * 8 + 4]);
                    const float i0 = s_in[ic][ky * D + 0][tx + kx * D];
                    const float i1 = s_in[ic][ky * D + 1][tx + kx * D];
                    const float i2 = s_in[ic][ky * D + 2][tx + kx * D];
                    const float i3 = s_in[ic][ky * D + 3][tx + kx * D];
                    float w8[8] = {wlo.x, wlo.y, wlo.z, wlo.w, whi.x, whi.y, whi.z, whi.w};
                    #pragma unroll
                    for (int o = 0; o < 8; o++) {
                        acc[o][0] += w8[o] * i0;
                        acc[o][1] += w8[o] * i1;
                        acc[o][2] += w8[o] * i2;
                        acc[o][3] += w8[o] * i3;
                    }
                }
            }
        }
        __syncthreads();
    }

    // bias + relu + max over this thread's 8 channels
    float m[4];
    #pragma unroll
    for (int r = 0; r < 4; r++) m[r] = 0.f;  // relu => values >= 0
    #pragma unroll
    for (int o = 0; o < 8; o++) {
        const float bv = bias[ty * 8 + o];
        #pragma unroll
        for (int r = 0; r < 4; r++)
            m[r] = fmaxf(m[r], fmaxf(acc[o][r] + bv, 0.f));
    }
    #pragma unroll
    for (int r = 0; r < 4; r++) s_red[ty][r * 16 + tx] = m[r];
    __syncthreads();

    if (tid < 64) {
        float mm = s_red[0][tid];
        #pragma unroll
        for (int t = 1; t < 8; t++) mm = fmaxf(mm, s_red[t][tid]);
        const int r = tid >> 4, c = tid & 15;
        const int oy = rowBase + r, ox = colBase + c;
        if (oy < MAPH && ox < MAPH)
            g_bmax[((br * NBATCH + b) * MAPH + oy) * MAPH + ox] = mm;
    }
}

// Cross-branch max + sigmoid + clip
__global__ void final_k(float* __restrict__ out)
{
    int i = blockIdx.x * blockDim.x + threadIdx.x;
    const int NPB = MAPH * MAPH;           // 9216
    if (i >= NBATCH * NPB) return;
    int b = i / NPB, p = i - b * NPB;
    float m = g_bmax[b * NPB + p];
    #pragma unroll
    for (int br = 1; br < NBR; br++)
        m = fmaxf(m, g_bmax[(br * NBATCH + b) * NPB + p]);
    float s = 1.f / (1.f + expf(-m));
    out[i] = fminf(fmaxf(s, 0.0001f), 0.9999f);
}

// ---------------------------------------------------------------------------
// Launch. Inputs (metadata order): x, perms(unused), dcn_w, dcn_b, conv2_w,
// conv2_b, conv3_w, conv3_b, bn_gamma, bn_beta, bn_mean, bn_var
// ---------------------------------------------------------------------------
extern "C" void kernel_launch(void* const* d_in, const int* in_sizes, int n_in,
                              void* d_out, int out_size)
{
    const float* x     = (const float*)d_in[0];
    const float* dcn_w = (const float*)d_in[2];
    const float* dcn_b = (const float*)d_in[3];
    const float* c2w   = (const float*)d_in[4];
    const float* c2b   = (const float*)d_in[5];
    const float* c3w   = (const float*)d_in[6];
    const float* c3b   = (const float*)d_in[7];
    const float* gam   = (const float*)d_in[8];
    const float* bet   = (const float*)d_in[9];
    const float* mu    = (const float*)d_in[10];
    const float* va    = (const float*)d_in[11];

    const int prepN = NBR * WSET + 2 * (4 * WSET) + 192; // 590016
    prep_kernel<<<(prepN + 255) / 256, 256>>>(dcn_w, dcn_b, c2w, c2b, c3w, c3b,
                                              gam, bet, mu, va);

    // Stage 1: even branches 96 -> 96 (pad 1, dil 1); odd: 96 (+5 halo) -> 104
    conv_mid_k<1, 1><<<dim3(6, 24, 32), 128>>>(x, 96, 96, 96, 1, 0);
    conv_mid_k<1, 1><<<dim3(7, 26, 32), 128>>>(x, 96, 104, 104, 5, 1);

    // Stage 2 (dil 2): even 96 -> 96 (pad 2); odd 104 -> 100 (valid)
    conv_mid_k<2, 2><<<dim3(6, 24, 32), 128>>>(nullptr, 96, 96, 96, 2, 0);
    conv_mid_k<2, 2><<<dim3(7, 25, 32), 128>>>(nullptr, 104, 100, 100, 0, 1);

    // Stage 3 (dil 2) + per-branch channel max: even 96 -> 96; odd 100 -> 96
    conv_last_k<<<dim3(6, 24, 32), 128>>>(96, 2, 0);
    conv_last_k<<<dim3(6, 24, 32), 128>>>(100, 0, 1);

    final_k<<<(NBATCH * MAPH * MAPH + 255) / 256, 256>>>((float*)d_out);
}

// round 3
// speedup vs baseline: 2.1350x; 2.1350x over previous
#include <cuda_runtime.h>
#include <cstdint>
#include <math.h>

// ---------------------------------------------------------------------------
// Problem constants
// ---------------------------------------------------------------------------
#define NBATCH 8
#define NCH    64
#define MAPH   96
#define NBR    8
#define BSTR   104
#define BCHS   (BSTR*BSTR)
#define WSET   36864            // floats per weight set (64 oc x 576 k), fragment layout
#define CPAD   68               // channel-last padding (68 mod 32 = 4 -> conflict-free)

// ---------------------------------------------------------------------------
// Device-global scratch
// ---------------------------------------------------------------------------
__device__ float g_buf1[(size_t)NBR*NBATCH*NCH*BCHS];
__device__ float g_buf2[(size_t)NBR*NBATCH*NCH*BCHS];
__device__ float g_bmax[NBR*NBATCH*MAPH*MAPH];
__device__ __align__(16) float g_w1[8*WSET];   // stage1, per branch (perm+rot+BN folded)
__device__ __align__(16) float g_w2[4*WSET];   // stage2, per rotation
__device__ __align__(16) float g_w3[4*WSET];   // stage3, per rotation
__device__ float g_bias[3*64];

// ---------------------------------------------------------------------------
// Helpers
// ---------------------------------------------------------------------------
__device__ __forceinline__ void rotmap(int k, int A, int B, int& sa, int& sb) {
    switch (k & 3) {
        case 0: sa = A;     sb = B;     break;
        case 1: sa = 2 - B; sb = A;     break;
        case 2: sa = 2 - A; sb = 2 - B; break;
        default: sa = B;    sb = 2 - A; break;
    }
}
__device__ __forceinline__ float to_tf32_rna(float v) {
    uint32_t u;
    asm("cvt.rna.tf32.f32 %0, %1;" : "=r"(u) : "f"(v));
    return __uint_as_float(u);
}
__device__ __forceinline__ void mma_tf32(float& c0, float& c1, float& c2, float& c3,
                                         float a0, float a1, float a2, float a3,
                                         float b0, float b1) {
    asm volatile(
        "mma.sync.aligned.m16n8k8.row.col.f32.tf32.tf32.f32 "
        "{%0,%1,%2,%3}, {%4,%5,%6,%7}, {%8,%9}, {%0,%1,%2,%3};"
        : "+f"(c0), "+f"(c1), "+f"(c2), "+f"(c3)
        : "r"(__float_as_uint(a0)), "r"(__float_as_uint(a1)),
          "r"(__float_as_uint(a2)), "r"(__float_as_uint(a3)),
          "r"(__float_as_uint(b0)), "r"(__float_as_uint(b1)));
}

// ---------------------------------------------------------------------------
// Weight prep: fold BN + rotation + (stage1) channel-roll perm; emit the
// mma.sync B-fragment layout directly:
//   dest idx = (((tap*8 + k8)*8 + ntile)*32 + lane)*2 + r
//   element  = W[oc = ntile*8 + lane/4][ic = k8*8 + lane%4 + 4r] at tap,
//   rounded to tf32 (cvt.rna).
// ---------------------------------------------------------------------------
__global__ void prep_kernel(
    const float* __restrict__ dcn_w, const float* __restrict__ dcn_b,
    const float* __restrict__ c2w,   const float* __restrict__ c2b,
    const float* __restrict__ c3w,   const float* __restrict__ c3b,
    const float* __restrict__ gam,   const float* __restrict__ bet,
    const float* __restrict__ mu,    const float* __restrict__ va)
{
    int id = blockIdx.x * blockDim.x + threadIdx.x;
    const int W1N = 8 * WSET, W2N = 4 * WSET;

    if (id < W1N + 2 * W2N) {
        int setBase, set;              // which weight array, which set inside it
        float* dst;
        const float* src;
        int bnOff;
        if (id < W1N)                  { dst = g_w1; src = dcn_w; bnOff = 0;   setBase = id; }
        else if (id < W1N + W2N)       { dst = g_w2; src = c2w;   bnOff = 64;  setBase = id - W1N; }
        else                           { dst = g_w3; src = c3w;   bnOff = 128; setBase = id - W1N - W2N; }
        set = setBase / WSET;
        int e   = setBase % WSET;
        int r    = e & 1;
        int lane = (e >> 1) & 31;
        int nt   = (e >> 6) & 7;
        int k8   = (e >> 9) & 7;
        int tap  = e >> 12;            // 0..8
        int oc = nt * 8 + (lane >> 2);
        int ic = k8 * 8 + (lane & 3) + 4 * r;
        int sa, sb; rotmap(set & 3, tap / 3, tap % 3, sa, sb);
        int sc = (bnOff == 0) ? ((ic + 8 * set) & 63) : ic;   // stage1 channel roll
        float scale = gam[bnOff + oc] * rsqrtf(va[bnOff + oc] + 1e-5f);
        dst[setBase] = to_tf32_rna(src[((oc * 64 + sc) * 3 + sa) * 3 + sb] * scale);
        return;
    }
    id -= W1N + 2 * W2N;
    if (id < 192) {
        int s = id / 64, oc = id & 63;
        float scale = gam[s * 64 + oc] * rsqrtf(va[s * 64 + oc] + 1e-5f);
        const float* cb = (s == 0) ? dcn_b : ((s == 1) ? c2b : c3b);
        g_bias[id] = cb[oc] * scale + bet[s * 64 + oc] - mu[s * 64 + oc] * scale;
    }
}

// ---------------------------------------------------------------------------
// Conv kernel: tf32 mma.sync implicit GEMM.
// Block = 256 threads = 8 warps (warpM 0..3, warpN 0..1).
// Pixel tile = 128 px (8 rows x 16 cols). Warp tile = 32 px x 32 oc.
// K = 576 as 9 taps x 8 channel-blocks of 8.
// grid = (maxRowTiles, batch, 8 branches); per-branch geometry from parity.
// ---------------------------------------------------------------------------
template<int D, int STAGE>
__global__ void __launch_bounds__(256, 1)
conv_mma(const float* __restrict__ xin)
{
    constexpr int R = 8 + 2 * D;       // patch rows
    constexpr int C = 16 + 2 * D;      // patch cols
    constexpr int INSZ = R * C * CPAD;

    extern __shared__ float sm[];
    float* sW    = sm;                  // WSET floats
    float* sIn   = sm + WSET;           // INSZ floats, layout [(r*C+c)*CPAD + ic]
    float* sBias = sIn + INSZ;          // 64
    float* sRed  = sBias + 64;          // 256 (stage 3)

    const int tid  = threadIdx.x;
    const int lane = tid & 31;
    const int wid  = tid >> 5;
    const int warpM = wid & 3;
    const int warpN = wid >> 2;

    const int br = blockIdx.z;
    const int b  = blockIdx.y;
    const int odd = br & 1;

    int pad, inValid, outH;
    if (STAGE == 1) { pad = odd ? 5 : 1; inValid = 96;             outH = odd ? 104 : 96; }
    else if (STAGE == 2) { pad = odd ? 0 : 2; inValid = odd ? 104 : 96; outH = odd ? 100 : 96; }
    else            { pad = odd ? 0 : 2; inValid = odd ? 100 : 96; outH = 96; }
    const int outW = outH;
    const int rowTiles = (outH + 7) >> 3;
    const int colTiles = (outW + 15) >> 4;
    const int rowTile = blockIdx.x;
    if (rowTile >= rowTiles) return;    // uniform per block

    const int STRIDE = (STAGE == 1) ? MAPH : BSTR;
    const int CHS = STRIDE * STRIDE;
    const float* inp = (STAGE == 1)
        ? (xin + (size_t)b * NCH * (MAPH * MAPH))
        : (((STAGE == 2) ? g_buf1 : g_buf2) + (size_t)(br * NBATCH + b) * NCH * BCHS);
    float* outp = ((STAGE == 1) ? g_buf1 : g_buf2)
                  + (size_t)(br * NBATCH + b) * NCH * BCHS;
    const float* wsrc = (STAGE == 1) ? (g_w1 + br * WSET)
                       : (STAGE == 2) ? (g_w2 + (br & 3) * WSET)
                                      : (g_w3 + (br & 3) * WSET);

    // ---- stage weights (fragment layout, linear copy) + bias ----
    {
        uint4* wd = (uint4*)sW;
        const uint4* ws = (const uint4*)wsrc;
        #pragma unroll 4
        for (int i = tid; i < WSET / 4; i += 256) wd[i] = ws[i];
        if (tid < 64) sBias[tid] = g_bias[(STAGE - 1) * 64 + tid];
    }

    const int rowBase = rowTile * 8;
    const int g  = lane >> 2;           // groupID
    const int t4 = lane & 3;

    for (int ct = 0; ct < colTiles; ct++) {
        const int colBase = ct * 16;
        __syncthreads();

        // ---- load input patch, channel-last padded, zero OOB ----
        for (int i = tid; i < 64 * R * C; i += 256) {
            int ic  = i / (R * C);
            int rem = i - ic * (R * C);
            int r = rem / C;
            int c = rem - r * C;
            int gy = rowBase + r - pad;
            int gx = colBase + c - pad;
            float v = 0.f;
            if ((unsigned)gy < (unsigned)inValid && (unsigned)gx < (unsigned)inValid)
                v = inp[(size_t)ic * CHS + gy * STRIDE + gx];
            sIn[(r * C + c) * CPAD + ic] = v;
        }
        __syncthreads();

        // ---- GEMM: 128px x 64oc x 576 ----
        float acc[2][4][4];
        #pragma unroll
        for (int mt = 0; mt < 2; mt++)
            #pragma unroll
            for (int nt = 0; nt < 4; nt++)
                #pragma unroll
                for (int q = 0; q < 4; q++) acc[mt][nt][q] = 0.f;

        #pragma unroll 1
        for (int tap = 0; tap < 9; tap++) {
            const int dy = (tap / 3) * D, dx = (tap % 3) * D;
            // A pointers: pixel row pr = warpM*2 + mt; pc = g (+8)
            const float* pA0 = sIn + ((warpM * 2 + 0 + dy) * C + dx + g) * CPAD + t4;
            const float* pA1 = pA0 + C * CPAD;     // mt = 1
            const float* pB  = sW + ((tap * 8) * 8 + warpN * 4) * 64 + lane * 2;

            #pragma unroll
            for (int k8 = 0; k8 < 8; k8++) {
                const int ko = k8 * 8;
                float a00 = pA0[ko],            a02 = pA0[ko + 4];
                float a01 = pA0[8 * CPAD + ko], a03 = pA0[8 * CPAD + ko + 4];
                float a10 = pA1[ko],            a12 = pA1[ko + 4];
                float a11 = pA1[8 * CPAD + ko], a13 = pA1[8 * CPAD + ko + 4];
                const float* pBk = pB + k8 * 8 * 64;
                #pragma unroll
                for (int nt = 0; nt < 4; nt++) {
                    float2 bb = *(const float2*)(pBk + nt * 64);
                    mma_tf32(acc[0][nt][0], acc[0][nt][1], acc[0][nt][2], acc[0][nt][3],
                             a00, a01, a02, a03, bb.x, bb.y);
                    mma_tf32(acc[1][nt][0], acc[1][nt][1], acc[1][nt][2], acc[1][nt][3],
                             a10, a11, a12, a13, bb.x, bb.y);
                }
            }
        }

        // ---- epilogue ----
        if (STAGE < 3) {
            #pragma unroll
            for (int mt = 0; mt < 2; mt++) {
                const int oyA = rowBase + warpM * 2 + mt;   // all 4 C-rows same oy row? no:
                // px0 = warpM*32 + mt*16 + g  -> oy = rowBase + (px>>4), ox = colBase + (px&15)
                const int px0 = warpM * 32 + mt * 16 + g;   // c0,c1
                const int oy = rowBase + (px0 >> 4);
                const int ox0 = colBase + (px0 & 15);
                const int ox1 = ox0 + 8;                     // px0+8 (c2,c3)
                (void)oyA;
                if (oy < outH) {
                    #pragma unroll
                    for (int nt = 0; nt < 4; nt++) {
                        const int oc = warpN * 32 + nt * 8 + 2 * t4;
                        const float b0 = sBias[oc], b1 = sBias[oc + 1];
                        if (ox0 < outW) {
                            outp[(size_t)oc * BCHS + oy * BSTR + ox0] =
                                fmaxf(acc[mt][nt][0] + b0, 0.f);
                            outp[(size_t)(oc + 1) * BCHS + oy * BSTR + ox0] =
                                fmaxf(acc[mt][nt][1] + b1, 0.f);
                        }
                        if (ox1 < outW) {
                            outp[(size_t)oc * BCHS + oy * BSTR + ox1] =
                                fmaxf(acc[mt][nt][2] + b0, 0.f);
                            outp[(size_t)(oc + 1) * BCHS + oy * BSTR + ox1] =
                                fmaxf(acc[mt][nt][3] + b1, 0.f);
                        }
                    }
                }
            }
        } else {
            // bias + relu + channel-max
            #pragma unroll
            for (int mt = 0; mt < 2; mt++) {
                float v0 = 0.f, v1 = 0.f;
                #pragma unroll
                for (int nt = 0; nt < 4; nt++) {
                    const int oc = warpN * 32 + nt * 8 + 2 * t4;
                    const float b0 = sBias[oc], b1 = sBias[oc + 1];
                    v0 = fmaxf(v0, fmaxf(acc[mt][nt][0] + b0, acc[mt][nt][1] + b1));
                    v1 = fmaxf(v1, fmaxf(acc[mt][nt][2] + b0, acc[mt][nt][3] + b1));
                }
                // reduce over the 4 lanes sharing this pixel (lane&3 varies oc)
                v0 = fmaxf(v0, __shfl_xor_sync(0xFFFFFFFF, v0, 1));
                v0 = fmaxf(v0, __shfl_xor_sync(0xFFFFFFFF, v0, 2));
                v1 = fmaxf(v1, __shfl_xor_sync(0xFFFFFFFF, v1, 1));
                v1 = fmaxf(v1, __shfl_xor_sync(0xFFFFFFFF, v1, 2));
                if (t4 == 0) {
                    const int px0 = warpM * 32 + mt * 16 + g;
                    sRed[px0 * 2 + warpN] = v0;
                    sRed[(px0 + 8) * 2 + warpN] = v1;
                }
            }
            __syncthreads();
            if (tid < 128) {
                const float m = fmaxf(sRed[tid * 2], sRed[tid * 2 + 1]);
                const int oy = rowBase + (tid >> 4);
                const int ox = colBase + (tid & 15);
                if (oy < MAPH && ox < MAPH)
                    g_bmax[((br * NBATCH + b) * MAPH + oy) * MAPH + ox] = m;
            }
        }
    }
}

// ---------------------------------------------------------------------------
// Cross-branch max + sigmoid + clip
// ---------------------------------------------------------------------------
__global__ void final_k(float* __restrict__ out)
{
    int i = blockIdx.x * blockDim.x + threadIdx.x;
    const int NPB = MAPH * MAPH;
    if (i >= NBATCH * NPB) return;
    int b = i / NPB, p = i - b * NPB;
    float m = g_bmax[b * NPB + p];
    #pragma unroll
    for (int br = 1; br < NBR; br++)
        m = fmaxf(m, g_bmax[(br * NBATCH + b) * NPB + p]);
    float s = 1.f / (1.f + expf(-m));
    out[i] = fminf(fmaxf(s, 0.0001f), 0.9999f);
}

// ---------------------------------------------------------------------------
// Launch
// ---------------------------------------------------------------------------
extern "C" void kernel_launch(void* const* d_in, const int* in_sizes, int n_in,
                              void* d_out, int out_size)
{
    const float* x     = (const float*)d_in[0];
    const float* dcn_w = (const float*)d_in[2];
    const float* dcn_b = (const float*)d_in[3];
    const float* c2w   = (const float*)d_in[4];
    const float* c2b   = (const float*)d_in[5];
    const float* c3w   = (const float*)d_in[6];
    const float* c3b   = (const float*)d_in[7];
    const float* gam   = (const float*)d_in[8];
    const float* bet   = (const float*)d_in[9];
    const float* mu    = (const float*)d_in[10];
    const float* va    = (const float*)d_in[11];

    constexpr int SMEM_D1 = (WSET + (10 * 18) * CPAD + 64 + 256) * 4;
    constexpr int SMEM_D2 = (WSET + (12 * 20) * CPAD + 64 + 256) * 4;

    cudaFuncSetAttribute((const void*)conv_mma<1, 1>,
                         cudaFuncAttributeMaxDynamicSharedMemorySize, SMEM_D1);
    cudaFuncSetAttribute((const void*)conv_mma<2, 2>,
                         cudaFuncAttributeMaxDynamicSharedMemorySize, SMEM_D2);
    cudaFuncSetAttribute((const void*)conv_mma<2, 3>,
                         cudaFuncAttributeMaxDynamicSharedMemorySize, SMEM_D2);

    const int prepN = 16 * WSET + 192;
    prep_kernel<<<(prepN + 255) / 256, 256>>>(dcn_w, dcn_b, c2w, c2b, c3w, c3b,
                                              gam, bet, mu, va);

    // Stage 1 (D=1): even 96->96 (pad1), odd 96->104 (halo 5). max rowTiles = 13
    conv_mma<1, 1><<<dim3(13, NBATCH, NBR), 256, SMEM_D1>>>(x);
    // Stage 2 (D=2): even 96->96 (pad2), odd 104->100 (valid). max rowTiles = 13
    conv_mma<2, 2><<<dim3(13, NBATCH, NBR), 256, SMEM_D2>>>(nullptr);
    // Stage 3 (D=2) + channel max: even 96->96, odd 100->96. rowTiles = 12
    conv_mma<2, 3><<<dim3(12, NBATCH, NBR), 256, SMEM_D2>>>(nullptr);

    final_k<<<(NBATCH * MAPH * MAPH + 255) / 256, 256>>>((float*)d_out);
}

// round 4
// speedup vs baseline: 2.5913x; 1.2137x over previous
#include <cuda_runtime.h>
#include <cstdint>
#include <math.h>

// ---------------------------------------------------------------------------
// Problem constants
// ---------------------------------------------------------------------------
#define NBATCH 8
#define NCH    64
#define MAPH   96
#define NBR    8
#define BSTR   104
#define BCHS   (BSTR*BSTR)
#define WSET   36864            // floats per weight set (64 oc x 576 k), fragment layout
#define CPAD   68               // channel-last padding (68 mod 32 = 4 -> conflict-free)

// ---------------------------------------------------------------------------
// Device-global scratch
// ---------------------------------------------------------------------------
__device__ float g_buf1[(size_t)NBR*NBATCH*NCH*BCHS];
__device__ float g_buf2[(size_t)NBR*NBATCH*NCH*BCHS];
__device__ float g_bmax[NBR*NBATCH*MAPH*MAPH];
__device__ __align__(16) float g_w1[8*WSET];   // stage1, per branch (perm+rot+BN folded)
__device__ __align__(16) float g_w2[4*WSET];   // stage2, per rotation
__device__ __align__(16) float g_w3[4*WSET];   // stage3, per rotation
__device__ float g_bias[3*64];

// ---------------------------------------------------------------------------
// Helpers
// ---------------------------------------------------------------------------
__device__ __forceinline__ void rotmap(int k, int A, int B, int& sa, int& sb) {
    switch (k & 3) {
        case 0: sa = A;     sb = B;     break;
        case 1: sa = 2 - B; sb = A;     break;
        case 2: sa = 2 - A; sb = 2 - B; break;
        default: sa = B;    sb = 2 - A; break;
    }
}
__device__ __forceinline__ float to_tf32_rna(float v) {
    uint32_t u;
    asm("cvt.rna.tf32.f32 %0, %1;" : "=r"(u) : "f"(v));
    return __uint_as_float(u);
}
__device__ __forceinline__ void mma_tf32(float& c0, float& c1, float& c2, float& c3,
                                         float a0, float a1, float a2, float a3,
                                         float b0, float b1) {
    asm volatile(
        "mma.sync.aligned.m16n8k8.row.col.f32.tf32.tf32.f32 "
        "{%0,%1,%2,%3}, {%4,%5,%6,%7}, {%8,%9}, {%0,%1,%2,%3};"
        : "+f"(c0), "+f"(c1), "+f"(c2), "+f"(c3)
        : "r"(__float_as_uint(a0)), "r"(__float_as_uint(a1)),
          "r"(__float_as_uint(a2)), "r"(__float_as_uint(a3)),
          "r"(__float_as_uint(b0)), "r"(__float_as_uint(b1)));
}

// ---------------------------------------------------------------------------
// Weight prep: fold BN + rotation + (stage1) channel-roll perm; emit the
// mma.sync B-fragment layout directly:
//   dest idx = (((tap*8 + k8)*8 + ntile)*32 + lane)*2 + r
//   element  = W[oc = ntile*8 + lane/4][ic = k8*8 + lane%4 + 4r] at tap,
//   rounded to tf32 (cvt.rna).
// ---------------------------------------------------------------------------
__global__ void prep_kernel(
    const float* __restrict__ dcn_w, const float* __restrict__ dcn_b,
    const float* __restrict__ c2w,   const float* __restrict__ c2b,
    const float* __restrict__ c3w,   const float* __restrict__ c3b,
    const float* __restrict__ gam,   const float* __restrict__ bet,
    const float* __restrict__ mu,    const float* __restrict__ va)
{
    int id = blockIdx.x * blockDim.x + threadIdx.x;
    const int W1N = 8 * WSET, W2N = 4 * WSET;

    if (id < W1N + 2 * W2N) {
        int setBase, set;
        float* dst;
        const float* src;
        int bnOff;
        if (id < W1N)                  { dst = g_w1; src = dcn_w; bnOff = 0;   setBase = id; }
        else if (id < W1N + W2N)       { dst = g_w2; src = c2w;   bnOff = 64;  setBase = id - W1N; }
        else                           { dst = g_w3; src = c3w;   bnOff = 128; setBase = id - W1N - W2N; }
        set = setBase / WSET;
        int e   = setBase % WSET;
        int r    = e & 1;
        int lane = (e >> 1) & 31;
        int nt   = (e >> 6) & 7;
        int k8   = (e >> 9) & 7;
        int tap  = e >> 12;            // 0..8
        int oc = nt * 8 + (lane >> 2);
        int ic = k8 * 8 + (lane & 3) + 4 * r;
        int sa, sb; rotmap(set & 3, tap / 3, tap % 3, sa, sb);
        int sc = (bnOff == 0) ? ((ic + 8 * set) & 63) : ic;   // stage1 channel roll
        float scale = gam[bnOff + oc] * rsqrtf(va[bnOff + oc] + 1e-5f);
        dst[setBase] = to_tf32_rna(src[((oc * 64 + sc) * 3 + sa) * 3 + sb] * scale);
        return;
    }
    id -= W1N + 2 * W2N;
    if (id < 192) {
        int s = id / 64, oc = id & 63;
        float scale = gam[s * 64 + oc] * rsqrtf(va[s * 64 + oc] + 1e-5f);
        const float* cb = (s == 0) ? dcn_b : ((s == 1) ? c2b : c3b);
        g_bias[id] = cb[oc] * scale + bet[s * 64 + oc] - mu[s * 64 + oc] * scale;
    }
}

// ---------------------------------------------------------------------------
// Conv kernel: tf32 mma.sync implicit GEMM, split-K over taps.
// Block = 512 threads = 16 warps = 2 warpgroups of 8 warps.
//   wg1 (warps 8..15): taps 0..4;  wg0 (warps 0..7): taps 5..8 + epilogue.
// Within a wg: warpM 0..3, warpN 0..1; warp tile 32px x 32oc.
// Pixel tile = 128 px (8 rows x 16 cols); K = 576 = 9 taps x 8 k8-blocks.
// wg1 spills accs to SMEM staging (aliased on patch buffer), wg0 adds.
// ---------------------------------------------------------------------------
template<int D, int STAGE>
__global__ void __launch_bounds__(512, 1)
conv_mma(const float* __restrict__ xin)
{
    constexpr int R = 8 + 2 * D;       // patch rows
    constexpr int C = 16 + 2 * D;      // patch cols
    constexpr int INSZ = R * C * CPAD; // >= 8192 floats (32KB) for staging alias

    extern __shared__ float sm[];
    float* sW    = sm;                  // WSET floats
    float* sIn   = sm + WSET;           // INSZ floats, layout [(r*C+c)*CPAD + ic]
    float* sBias = sIn + INSZ;          // 64
    float* sRed  = sBias + 64;          // 256 (stage 3)
    float* sStage = sIn;                // 32KB staging, aliases patch (dead there)

    const int tid  = threadIdx.x;
    const int lane = tid & 31;
    const int wid  = tid >> 5;          // 0..15
    const int wg   = wid >> 3;          // 0 / 1
    const int wtid = tid & 255;         // thread id within warpgroup
    const int wloc = wid & 7;
    const int warpM = wloc & 3;
    const int warpN = wloc >> 2;

    const int br = blockIdx.z;
    const int b  = blockIdx.y;
    const int odd = br & 1;

    int pad, inValid, outH;
    if (STAGE == 1)      { pad = odd ? 5 : 1; inValid = 96;             outH = odd ? 104 : 96; }
    else if (STAGE == 2) { pad = odd ? 0 : 2; inValid = odd ? 104 : 96; outH = odd ? 100 : 96; }
    else                 { pad = odd ? 0 : 2; inValid = odd ? 100 : 96; outH = 96; }
    const int outW = outH;
    const int rowTiles = (outH + 7) >> 3;
    const int colTiles = (outW + 15) >> 4;
    const int rowTile = blockIdx.x;
    if (rowTile >= rowTiles) return;    // uniform per block

    const int STRIDE = (STAGE == 1) ? MAPH : BSTR;
    const int CHS = STRIDE * STRIDE;
    const float* inp = (STAGE == 1)
        ? (xin + (size_t)b * NCH * (MAPH * MAPH))
        : (((STAGE == 2) ? g_buf1 : g_buf2) + (size_t)(br * NBATCH + b) * NCH * BCHS);
    float* outp = ((STAGE == 1) ? g_buf1 : g_buf2)
                  + (size_t)(br * NBATCH + b) * NCH * BCHS;
    const float* wsrc = (STAGE == 1) ? (g_w1 + br * WSET)
                       : (STAGE == 2) ? (g_w2 + (br & 3) * WSET)
                                      : (g_w3 + (br & 3) * WSET);

    // ---- stage weights (fragment layout, linear copy) + bias ----
    {
        uint4* wd = (uint4*)sW;
        const uint4* ws = (const uint4*)wsrc;
        #pragma unroll 4
        for (int i = tid; i < WSET / 4; i += 512) wd[i] = ws[i];
        if (tid < 64) sBias[tid] = g_bias[(STAGE - 1) * 64 + tid];
    }

    const int rowBase = rowTile * 8;
    const int g  = lane >> 2;           // groupID
    const int t4 = lane & 3;

    const int tapBeg = wg ? 0 : 5;      // wg1: 5 taps; wg0: 4 taps (+ epilogue)
    const int tapEnd = wg ? 5 : 9;

    for (int ct = 0; ct < colTiles; ct++) {
        const int colBase = ct * 16;
        __syncthreads();   // staging reads (prev iter) done before patch overwrite

        // ---- load input patch, channel-last padded, zero OOB ----
        for (int i = tid; i < 64 * R * C; i += 512) {
            int ic  = i / (R * C);
            int rem = i - ic * (R * C);
            int r = rem / C;
            int c = rem - r * C;
            int gy = rowBase + r - pad;
            int gx = colBase + c - pad;
            float v = 0.f;
            if ((unsigned)gy < (unsigned)inValid && (unsigned)gx < (unsigned)inValid)
                v = inp[(size_t)ic * CHS + gy * STRIDE + gx];
            sIn[(r * C + c) * CPAD + ic] = v;
        }
        __syncthreads();

        // ---- GEMM: 128px x 64oc x (this wg's taps) ----
        float acc[2][4][4];
        #pragma unroll
        for (int mt = 0; mt < 2; mt++)
            #pragma unroll
            for (int nt = 0; nt < 4; nt++)
                #pragma unroll
                for (int q = 0; q < 4; q++) acc[mt][nt][q] = 0.f;

        #pragma unroll 1
        for (int tap = tapBeg; tap < tapEnd; tap++) {
            const int dy = (tap / 3) * D, dx = (tap % 3) * D;
            const float* pA0 = sIn + ((warpM * 2 + 0 + dy) * C + dx + g) * CPAD + t4;
            const float* pA1 = pA0 + C * CPAD;
            const float* pB  = sW + ((tap * 8) * 8 + warpN * 4) * 64 + lane * 2;

            #pragma unroll
            for (int k8 = 0; k8 < 8; k8++) {
                const int ko = k8 * 8;
                float a00 = pA0[ko],            a02 = pA0[ko + 4];
                float a01 = pA0[8 * CPAD + ko], a03 = pA0[8 * CPAD + ko + 4];
                float a10 = pA1[ko],            a12 = pA1[ko + 4];
                float a11 = pA1[8 * CPAD + ko], a13 = pA1[8 * CPAD + ko + 4];
                const float* pBk = pB + k8 * 8 * 64;
                #pragma unroll
                for (int nt = 0; nt < 4; nt++) {
                    float2 bb = *(const float2*)(pBk + nt * 64);
                    mma_tf32(acc[0][nt][0], acc[0][nt][1], acc[0][nt][2], acc[0][nt][3],
                             a00, a01, a02, a03, bb.x, bb.y);
                    mma_tf32(acc[1][nt][0], acc[1][nt][1], acc[1][nt][2], acc[1][nt][3],
                             a10, a11, a12, a13, bb.x, bb.y);
                }
            }
        }

        // ---- cross-warpgroup reduction: wg1 -> staging, wg0 adds ----
        __syncthreads();   // all reads of sIn complete (staging aliases it)
        if (wg == 1) {
            #pragma unroll
            for (int mt = 0; mt < 2; mt++)
                #pragma unroll
                for (int nt = 0; nt < 4; nt++)
                    #pragma unroll
                    for (int q = 0; q < 4; q++)
                        sStage[(mt * 16 + nt * 4 + q) * 256 + wtid] = acc[mt][nt][q];
        }
        __syncthreads();

        if (wg == 0) {
            #pragma unroll
            for (int mt = 0; mt < 2; mt++)
                #pragma unroll
                for (int nt = 0; nt < 4; nt++)
                    #pragma unroll
                    for (int q = 0; q < 4; q++)
                        acc[mt][nt][q] += sStage[(mt * 16 + nt * 4 + q) * 256 + wtid];

            // ---- epilogue (wg0 only) ----
            if (STAGE < 3) {
                #pragma unroll
                for (int mt = 0; mt < 2; mt++) {
                    const int px0 = warpM * 32 + mt * 16 + g;
                    const int oy = rowBase + (px0 >> 4);
                    const int ox0 = colBase + (px0 & 15);
                    const int ox1 = ox0 + 8;
                    if (oy < outH) {
                        #pragma unroll
                        for (int nt = 0; nt < 4; nt++) {
                            const int oc = warpN * 32 + nt * 8 + 2 * t4;
                            const float b0 = sBias[oc], b1 = sBias[oc + 1];
                            if (ox0 < outW) {
                                outp[(size_t)oc * BCHS + oy * BSTR + ox0] =
                                    fmaxf(acc[mt][nt][0] + b0, 0.f);
                                outp[(size_t)(oc + 1) * BCHS + oy * BSTR + ox0] =
                                    fmaxf(acc[mt][nt][1] + b1, 0.f);
                            }
                            if (ox1 < outW) {
                                outp[(size_t)oc * BCHS + oy * BSTR + ox1] =
                                    fmaxf(acc[mt][nt][2] + b0, 0.f);
                                outp[(size_t)(oc + 1) * BCHS + oy * BSTR + ox1] =
                                    fmaxf(acc[mt][nt][3] + b1, 0.f);
                            }
                        }
                    }
                }
            } else {
                #pragma unroll
                for (int mt = 0; mt < 2; mt++) {
                    float v0 = 0.f, v1 = 0.f;
                    #pragma unroll
                    for (int nt = 0; nt < 4; nt++) {
                        const int oc = warpN * 32 + nt * 8 + 2 * t4;
                        const float b0 = sBias[oc], b1 = sBias[oc + 1];
                        v0 = fmaxf(v0, fmaxf(acc[mt][nt][0] + b0, acc[mt][nt][1] + b1));
                        v1 = fmaxf(v1, fmaxf(acc[mt][nt][2] + b0, acc[mt][nt][3] + b1));
                    }
                    v0 = fmaxf(v0, __shfl_xor_sync(0xFFFFFFFF, v0, 1));
                    v0 = fmaxf(v0, __shfl_xor_sync(0xFFFFFFFF, v0, 2));
                    v1 = fmaxf(v1, __shfl_xor_sync(0xFFFFFFFF, v1, 1));
                    v1 = fmaxf(v1, __shfl_xor_sync(0xFFFFFFFF, v1, 2));
                    if (t4 == 0) {
                        const int px0 = warpM * 32 + mt * 16 + g;
                        sRed[px0 * 2 + warpN] = v0;
                        sRed[(px0 + 8) * 2 + warpN] = v1;
                    }
                }
            }
        }

        if (STAGE == 3) {
            __syncthreads();
            if (tid < 128) {
                const float m = fmaxf(sRed[tid * 2], sRed[tid * 2 + 1]);
                const int oy = rowBase + (tid >> 4);
                const int ox = colBase + (tid & 15);
                if (oy < MAPH && ox < MAPH)
                    g_bmax[((br * NBATCH + b) * MAPH + oy) * MAPH + ox] = m;
            }
        }
    }
}

// ---------------------------------------------------------------------------
// Cross-branch max + sigmoid + clip
// ---------------------------------------------------------------------------
__global__ void final_k(float* __restrict__ out)
{
    int i = blockIdx.x * blockDim.x + threadIdx.x;
    const int NPB = MAPH * MAPH;
    if (i >= NBATCH * NPB) return;
    int b = i / NPB, p = i - b * NPB;
    float m = g_bmax[b * NPB + p];
    #pragma unroll
    for (int br = 1; br < NBR; br++)
        m = fmaxf(m, g_bmax[(br * NBATCH + b) * NPB + p]);
    float s = 1.f / (1.f + expf(-m));
    out[i] = fminf(fmaxf(s, 0.0001f), 0.9999f);
}

// ---------------------------------------------------------------------------
// Launch
// ---------------------------------------------------------------------------
extern "C" void kernel_launch(void* const* d_in, const int* in_sizes, int n_in,
                              void* d_out, int out_size)
{
    const float* x     = (const float*)d_in[0];
    const float* dcn_w = (const float*)d_in[2];
    const float* dcn_b = (const float*)d_in[3];
    const float* c2w   = (const float*)d_in[4];
    const float* c2b   = (const float*)d_in[5];
    const float* c3w   = (const float*)d_in[6];
    const float* c3b   = (const float*)d_in[7];
    const float* gam   = (const float*)d_in[8];
    const float* bet   = (const float*)d_in[9];
    const float* mu    = (const float*)d_in[10];
    const float* va    = (const float*)d_in[11];

    constexpr int SMEM_D1 = (WSET + (10 * 18) * CPAD + 64 + 256) * 4;
    constexpr int SMEM_D2 = (WSET + (12 * 20) * CPAD + 64 + 256) * 4;

    cudaFuncSetAttribute((const void*)conv_mma<1, 1>,
                         cudaFuncAttributeMaxDynamicSharedMemorySize, SMEM_D1);
    cudaFuncSetAttribute((const void*)conv_mma<2, 2>,
                         cudaFuncAttributeMaxDynamicSharedMemorySize, SMEM_D2);
    cudaFuncSetAttribute((const void*)conv_mma<2, 3>,
                         cudaFuncAttributeMaxDynamicSharedMemorySize, SMEM_D2);

    const int prepN = 16 * WSET + 192;
    prep_kernel<<<(prepN + 255) / 256, 256>>>(dcn_w, dcn_b, c2w, c2b, c3w, c3b,
                                              gam, bet, mu, va);

    // Stage 1 (D=1): even 96->96 (pad1), odd 96->104 (halo 5). max rowTiles = 13
    conv_mma<1, 1><<<dim3(13, NBATCH, NBR), 512, SMEM_D1>>>(x);
    // Stage 2 (D=2): even 96->96 (pad2), odd 104->100 (valid). max rowTiles = 13
    conv_mma<2, 2><<<dim3(13, NBATCH, NBR), 512, SMEM_D2>>>(nullptr);
    // Stage 3 (D=2) + channel max: even 96->96, odd 100->96. rowTiles = 12
    conv_mma<2, 3><<<dim3(12, NBATCH, NBR), 512, SMEM_D2>>>(nullptr);

    final_k<<<(NBATCH * MAPH * MAPH + 255) / 256, 256>>>((float*)d_out);
}

// round 5
// speedup vs baseline: 4.3063x; 1.6619x over previous
#include <cuda_runtime.h>
#include <cuda_fp16.h>
#include <cstdint>
#include <math.h>

// ---------------------------------------------------------------------------
// Problem constants
// ---------------------------------------------------------------------------
#define NBATCH 8
#define NCH    64
#define MAPH   96
#define NBR    8
#define BSTR   104
#define BCHS   (BSTR*BSTR)
#define WSETW  18432            // uint32 fragment words per weight set (9*4*8*64)
#define CPADH  72               // halves per pixel row in patch (64 + pad)
#define CPADW  36               // 32-bit words per pixel ( (4g+t4)%32 distinct -> conflict-free )

// ---------------------------------------------------------------------------
// Device-global scratch (fp16 inter-stage buffers)
// ---------------------------------------------------------------------------
__device__ __half g_buf1[(size_t)NBR*NBATCH*NCH*BCHS];
__device__ __half g_buf2[(size_t)NBR*NBATCH*NCH*BCHS];
__device__ float  g_bmax[NBR*NBATCH*MAPH*MAPH];
__device__ __align__(16) uint32_t g_w1[8*WSETW];   // fp16 B-fragment images
__device__ __align__(16) uint32_t g_w2[4*WSETW];
__device__ __align__(16) uint32_t g_w3[4*WSETW];
__device__ float g_bias[3*64];

// ---------------------------------------------------------------------------
// Helpers
// ---------------------------------------------------------------------------
__device__ __forceinline__ void rotmap(int k, int A, int B, int& sa, int& sb) {
    switch (k & 3) {
        case 0: sa = A;     sb = B;     break;
        case 1: sa = 2 - B; sb = A;     break;
        case 2: sa = 2 - A; sb = 2 - B; break;
        default: sa = B;    sb = 2 - A; break;
    }
}
__device__ __forceinline__ void mma_f16(float& c0, float& c1, float& c2, float& c3,
                                        uint32_t a0, uint32_t a1, uint32_t a2, uint32_t a3,
                                        uint32_t b0, uint32_t b1) {
    asm volatile(
        "mma.sync.aligned.m16n8k16.row.col.f32.f16.f16.f32 "
        "{%0,%1,%2,%3}, {%4,%5,%6,%7}, {%8,%9}, {%0,%1,%2,%3};"
        : "+f"(c0), "+f"(c1), "+f"(c2), "+f"(c3)
        : "r"(a0), "r"(a1), "r"(a2), "r"(a3), "r"(b0), "r"(b1));
}

// ---------------------------------------------------------------------------
// Weight prep: fold BN + rotation + (stage1) channel-roll perm; emit fp16
// B-fragment words for mma.m16n8k16:
//   word idx e = ((tap*4 + k16)*8 + nt)*64 + lane*2 + r
//   halves    = W[oc = nt*8 + lane/4][ic = k16*16 + 2*(lane%4) + 8r + {0,1}]
// ---------------------------------------------------------------------------
__global__ void prep_kernel(
    const float* __restrict__ dcn_w, const float* __restrict__ dcn_b,
    const float* __restrict__ c2w,   const float* __restrict__ c2b,
    const float* __restrict__ c3w,   const float* __restrict__ c3b,
    const float* __restrict__ gam,   const float* __restrict__ bet,
    const float* __restrict__ mu,    const float* __restrict__ va)
{
    int id = blockIdx.x * blockDim.x + threadIdx.x;
    const int W1N = 8 * WSETW, W2N = 4 * WSETW;

    if (id < W1N + 2 * W2N) {
        int setBase;
        uint32_t* dst;
        const float* src;
        int bnOff;
        if (id < W1N)            { dst = g_w1; src = dcn_w; bnOff = 0;   setBase = id; }
        else if (id < W1N + W2N) { dst = g_w2; src = c2w;   bnOff = 64;  setBase = id - W1N; }
        else                     { dst = g_w3; src = c3w;   bnOff = 128; setBase = id - W1N - W2N; }
        int set = setBase / WSETW;
        int e   = setBase % WSETW;
        int r    = e & 1;
        int lane = (e >> 1) & 31;
        int nt   = (e >> 6) & 7;
        int k16  = (e >> 9) & 3;
        int tap  = e >> 11;            // 0..8
        int g  = lane >> 2;
        int t4 = lane & 3;
        int oc  = nt * 8 + g;
        int ic0 = k16 * 16 + 2 * t4 + 8 * r;
        int sa, sb; rotmap(set & 3, tap / 3, tap % 3, sa, sb);
        float scale = gam[bnOff + oc] * rsqrtf(va[bnOff + oc] + 1e-5f);
        int sc0 = (bnOff == 0) ? ((ic0 + 8 * set) & 63) : ic0;
        int sc1 = (bnOff == 0) ? ((ic0 + 1 + 8 * set) & 63) : (ic0 + 1);
        float v0 = src[((oc * 64 + sc0) * 3 + sa) * 3 + sb] * scale;
        float v1 = src[((oc * 64 + sc1) * 3 + sa) * 3 + sb] * scale;
        uint32_t w = (uint32_t)__half_as_ushort(__float2half(v0))
                   | ((uint32_t)__half_as_ushort(__float2half(v1)) << 16);
        dst[setBase] = w;
        return;
    }
    id -= W1N + 2 * W2N;
    if (id < 192) {
        int s = id / 64, oc = id & 63;
        float scale = gam[s * 64 + oc] * rsqrtf(va[s * 64 + oc] + 1e-5f);
        const float* cb = (s == 0) ? dcn_b : ((s == 1) ? c2b : c3b);
        g_bias[id] = cb[oc] * scale + bet[s * 64 + oc] - mu[s * 64 + oc] * scale;
    }
}

// ---------------------------------------------------------------------------
// Conv kernel: fp16 mma.sync.m16n8k16 implicit GEMM.
// Block = 256 threads = 8 warps (warpM 0..3, warpN 0..1), 2 CTAs/SM.
// Pixel tile = 128 px (8 rows x 16 cols). Warp tile = 32 px (M) x 32 oc (N).
// K = 576 as 9 taps x 4 k16-blocks.
// ---------------------------------------------------------------------------
template<int D, int STAGE>
__global__ void __launch_bounds__(256, 2)
conv_mma(const float* __restrict__ xin)
{
    constexpr int R = 8 + 2 * D;          // patch rows
    constexpr int C = 16 + 2 * D;         // patch cols
    constexpr int PATCHH = R * C * CPADH; // halves

    extern __shared__ char sm[];
    uint32_t* sW   = (uint32_t*)sm;                        // 18432 words (73728B)
    __half*   sIn  = (__half*)(sm + 73728);                // patch
    float*    sBias = (float*)(sm + 73728 + PATCHH * 2);   // 64
    float*    sRed  = sBias + 64;                          // 256 (stage 3)

    const int tid  = threadIdx.x;
    const int lane = tid & 31;
    const int wid  = tid >> 5;
    const int warpM = wid & 3;
    const int warpN = wid >> 2;

    const int br = blockIdx.z;
    const int b  = blockIdx.y;
    const int odd = br & 1;

    int pad, inValid, outH;
    if (STAGE == 1)      { pad = odd ? 5 : 1; inValid = 96;             outH = odd ? 104 : 96; }
    else if (STAGE == 2) { pad = odd ? 0 : 2; inValid = odd ? 104 : 96; outH = odd ? 100 : 96; }
    else                 { pad = odd ? 0 : 2; inValid = odd ? 100 : 96; outH = 96; }
    const int outW = outH;
    const int rowTiles = (outH + 7) >> 3;
    const int colTiles = (outW + 15) >> 4;
    const int rowTile = blockIdx.x;
    if (rowTile >= rowTiles) return;      // uniform per block

    const int STRIDE = (STAGE == 1) ? MAPH : BSTR;
    const int CHS = STRIDE * STRIDE;
    const float*  inpF = (STAGE == 1) ? (xin + (size_t)b * NCH * (MAPH * MAPH)) : nullptr;
    const __half* inpH = (STAGE == 2) ? (g_buf1 + (size_t)(br * NBATCH + b) * NCH * BCHS)
                        : (STAGE == 3) ? (g_buf2 + (size_t)(br * NBATCH + b) * NCH * BCHS)
                                       : nullptr;
    __half* outp = ((STAGE == 1) ? g_buf1 : g_buf2)
                   + (size_t)(br * NBATCH + b) * NCH * BCHS;
    const uint32_t* wsrc = (STAGE == 1) ? (g_w1 + br * WSETW)
                          : (STAGE == 2) ? (g_w2 + (br & 3) * WSETW)
                                         : (g_w3 + (br & 3) * WSETW);

    // ---- stage weights (fragment words, linear copy) + bias ----
    {
        uint4* wd = (uint4*)sW;
        const uint4* ws = (const uint4*)wsrc;
        #pragma unroll 4
        for (int i = tid; i < WSETW / 4; i += 256) wd[i] = ws[i];
        if (tid < 64) sBias[tid] = g_bias[(STAGE - 1) * 64 + tid];
    }

    const int rowBase = rowTile * 8;
    const int g  = lane >> 2;
    const int t4 = lane & 3;
    const __half hzero = __ushort_as_half((unsigned short)0);

    const uint32_t* sInW = (const uint32_t*)sIn;

    for (int ct = 0; ct < colTiles; ct++) {
        const int colBase = ct * 16;
        __syncthreads();   // prior-iter reads of sIn done before overwrite

        // ---- load input patch (channel-last fp16, zero OOB) ----
        for (int i = tid; i < 64 * R * C; i += 256) {
            int ic  = i / (R * C);
            int rem = i - ic * (R * C);
            int r = rem / C;
            int c = rem - r * C;
            int gy = rowBase + r - pad;
            int gx = colBase + c - pad;
            __half v = hzero;
            if ((unsigned)gy < (unsigned)inValid && (unsigned)gx < (unsigned)inValid) {
                if (STAGE == 1) v = __float2half(inpF[(size_t)ic * CHS + gy * STRIDE + gx]);
                else            v = inpH[(size_t)ic * CHS + gy * STRIDE + gx];
            }
            sIn[(r * C + c) * CPADH + ic] = v;
        }
        __syncthreads();

        // ---- GEMM: 128px x 64oc x 576 (fp16, K16 steps) ----
        float acc[2][4][4];
        #pragma unroll
        for (int mt = 0; mt < 2; mt++)
            #pragma unroll
            for (int nt = 0; nt < 4; nt++)
                #pragma unroll
                for (int q = 0; q < 4; q++) acc[mt][nt][q] = 0.f;

        #pragma unroll 1
        for (int tap = 0; tap < 9; tap++) {
            const int dy = (tap / 3) * D, dx = (tap % 3) * D;
            const uint32_t* pA0 = sInW + ((warpM * 2 + 0 + dy) * C + dx + g) * CPADW + t4;
            const uint32_t* pA1 = pA0 + C * CPADW;
            const uint2* pB = (const uint2*)sW
                              + ((tap * 4) * 8 + warpN * 4) * 32 + lane;

            #pragma unroll
            for (int k16 = 0; k16 < 4; k16++) {
                const int ko = k16 * 8;
                uint32_t a00 = pA0[ko],           a02 = pA0[ko + 4];
                uint32_t a01 = pA0[ko + 8*CPADW], a03 = pA0[ko + 8*CPADW + 4];
                uint32_t a10 = pA1[ko],           a12 = pA1[ko + 4];
                uint32_t a11 = pA1[ko + 8*CPADW], a13 = pA1[ko + 8*CPADW + 4];
                const uint2* pBk = pB + k16 * 256;   // (k16*8 nt-slots)*32 lanes
                #pragma unroll
                for (int nt = 0; nt < 4; nt++) {
                    uint2 bb = pBk[nt * 32];
                    mma_f16(acc[0][nt][0], acc[0][nt][1], acc[0][nt][2], acc[0][nt][3],
                            a00, a01, a02, a03, bb.x, bb.y);
                    mma_f16(acc[1][nt][0], acc[1][nt][1], acc[1][nt][2], acc[1][nt][3],
                            a10, a11, a12, a13, bb.x, bb.y);
                }
            }
        }

        // ---- epilogue ----
        if (STAGE < 3) {
            #pragma unroll
            for (int mt = 0; mt < 2; mt++) {
                const int px0 = warpM * 32 + mt * 16 + g;
                const int oy = rowBase + (px0 >> 4);
                const int ox0 = colBase + (px0 & 15);
                const int ox1 = ox0 + 8;
                if (oy < outH) {
                    #pragma unroll
                    for (int nt = 0; nt < 4; nt++) {
                        const int oc = warpN * 32 + nt * 8 + 2 * t4;
                        const float b0 = sBias[oc], b1 = sBias[oc + 1];
                        if (ox0 < outW) {
                            outp[(size_t)oc * BCHS + oy * BSTR + ox0] =
                                __float2half(fmaxf(acc[mt][nt][0] + b0, 0.f));
                            outp[(size_t)(oc + 1) * BCHS + oy * BSTR + ox0] =
                                __float2half(fmaxf(acc[mt][nt][1] + b1, 0.f));
                        }
                        if (ox1 < outW) {
                            outp[(size_t)oc * BCHS + oy * BSTR + ox1] =
                                __float2half(fmaxf(acc[mt][nt][2] + b0, 0.f));
                            outp[(size_t)(oc + 1) * BCHS + oy * BSTR + ox1] =
                                __float2half(fmaxf(acc[mt][nt][3] + b1, 0.f));
                        }
                    }
                }
            }
        } else {
            #pragma unroll
            for (int mt = 0; mt < 2; mt++) {
                float v0 = 0.f, v1 = 0.f;
                #pragma unroll
                for (int nt = 0; nt < 4; nt++) {
                    const int oc = warpN * 32 + nt * 8 + 2 * t4;
                    const float b0 = sBias[oc], b1 = sBias[oc + 1];
                    v0 = fmaxf(v0, fmaxf(acc[mt][nt][0] + b0, acc[mt][nt][1] + b1));
                    v1 = fmaxf(v1, fmaxf(acc[mt][nt][2] + b0, acc[mt][nt][3] + b1));
                }
                v0 = fmaxf(v0, __shfl_xor_sync(0xFFFFFFFF, v0, 1));
                v0 = fmaxf(v0, __shfl_xor_sync(0xFFFFFFFF, v0, 2));
                v1 = fmaxf(v1, __shfl_xor_sync(0xFFFFFFFF, v1, 1));
                v1 = fmaxf(v1, __shfl_xor_sync(0xFFFFFFFF, v1, 2));
                if (t4 == 0) {
                    const int px0 = warpM * 32 + mt * 16 + g;
                    sRed[px0 * 2 + warpN] = v0;
                    sRed[(px0 + 8) * 2 + warpN] = v1;
                }
            }
            __syncthreads();
            if (tid < 128) {
                const float m = fmaxf(sRed[tid * 2], sRed[tid * 2 + 1]);
                const int oy = rowBase + (tid >> 4);
                const int ox = colBase + (tid & 15);
                if (oy < MAPH && ox < MAPH)
                    g_bmax[((br * NBATCH + b) * MAPH + oy) * MAPH + ox] = m;
            }
        }
    }
}

// ---------------------------------------------------------------------------
// Cross-branch max + sigmoid + clip
// ---------------------------------------------------------------------------
__global__ void final_k(float* __restrict__ out)
{
    int i = blockIdx.x * blockDim.x + threadIdx.x;
    const int NPB = MAPH * MAPH;
    if (i >= NBATCH * NPB) return;
    int b = i / NPB, p = i - b * NPB;
    float m = g_bmax[b * NPB + p];
    #pragma unroll
    for (int br = 1; br < NBR; br++)
        m = fmaxf(m, g_bmax[(br * NBATCH + b) * NPB + p]);
    float s = 1.f / (1.f + expf(-m));
    out[i] = fminf(fmaxf(s, 0.0001f), 0.9999f);
}

// ---------------------------------------------------------------------------
// Launch
// ---------------------------------------------------------------------------
extern "C" void kernel_launch(void* const* d_in, const int* in_sizes, int n_in,
                              void* d_out, int out_size)
{
    const float* x     = (const float*)d_in[0];
    const float* dcn_w = (const float*)d_in[2];
    const float* dcn_b = (const float*)d_in[3];
    const float* c2w   = (const float*)d_in[4];
    const float* c2b   = (const float*)d_in[5];
    const float* c3w   = (const float*)d_in[6];
    const float* c3b   = (const float*)d_in[7];
    const float* gam   = (const float*)d_in[8];
    const float* bet   = (const float*)d_in[9];
    const float* mu    = (const float*)d_in[10];
    const float* va    = (const float*)d_in[11];

    constexpr int SMEM_D1 = 73728 + (10 * 18 * CPADH) * 2 + 64 * 4 + 256 * 4;  // 100928
    constexpr int SMEM_D2 = 73728 + (12 * 20 * CPADH) * 2 + 64 * 4 + 256 * 4;  // 109568

    cudaFuncSetAttribute((const void*)conv_mma<1, 1>,
                         cudaFuncAttributeMaxDynamicSharedMemorySize, SMEM_D1);
    cudaFuncSetAttribute((const void*)conv_mma<2, 2>,
                         cudaFuncAttributeMaxDynamicSharedMemorySize, SMEM_D2);
    cudaFuncSetAttribute((const void*)conv_mma<2, 3>,
                         cudaFuncAttributeMaxDynamicSharedMemorySize, SMEM_D2);

    const int prepN = 16 * WSETW + 192;
    prep_kernel<<<(prepN + 255) / 256, 256>>>(dcn_w, dcn_b, c2w, c2b, c3w, c3b,
                                              gam, bet, mu, va);

    // Stage 1 (D=1): even 96->96 (pad1), odd 96->104 (halo 5). max rowTiles = 13
    conv_mma<1, 1><<<dim3(13, NBATCH, NBR), 256, SMEM_D1>>>(x);
    // Stage 2 (D=2): even 96->96 (pad2), odd 104->100 (valid). max rowTiles = 13
    conv_mma<2, 2><<<dim3(13, NBATCH, NBR), 256, SMEM_D2>>>(nullptr);
    // Stage 3 (D=2) + channel max: even 96->96, odd 100->96. rowTiles = 12
    conv_mma<2, 3><<<dim3(12, NBATCH, NBR), 256, SMEM_D2>>>(nullptr);

    final_k<<<(NBATCH * MAPH * MAPH + 255) / 256, 256>>>((float*)d_out);
}

// round 6
// speedup vs baseline: 7.2611x; 1.6861x over previous
#include <cuda_runtime.h>
#include <cuda_fp16.h>
#include <cstdint>
#include <math.h>

// ---------------------------------------------------------------------------
// Problem constants
// ---------------------------------------------------------------------------
#define NBATCH 8
#define NCH    64
#define MAPH   96
#define NBR    8
#define BSTR   104
#define BCHS   (BSTR*BSTR)
#define WSETW  18432            // uint32 fragment words per weight set (9*4*8*64)
#define CPADH  72               // halves per pixel in patch (64 + 8 pad) = 144B
#define PIXB   144              // bytes per patch pixel

// ---------------------------------------------------------------------------
// Device-global scratch (channel-last fp16 activations)
// ---------------------------------------------------------------------------
__device__ __align__(16) __half g_x16[(size_t)NBATCH*MAPH*MAPH*NCH];       // [b][pix][ic]
__device__ __align__(16) __half g_buf1[(size_t)NBR*NBATCH*BCHS*NCH];       // [(br,b)][pix][ic]
__device__ __align__(16) __half g_buf2[(size_t)NBR*NBATCH*BCHS*NCH];
__device__ float  g_bmax[NBR*NBATCH*MAPH*MAPH];
__device__ __align__(16) uint32_t g_w1[8*WSETW];   // fp16 B-fragment images
__device__ __align__(16) uint32_t g_w2[4*WSETW];
__device__ __align__(16) uint32_t g_w3[4*WSETW];
__device__ float g_bias[3*64];

// ---------------------------------------------------------------------------
// Helpers
// ---------------------------------------------------------------------------
__device__ __forceinline__ void rotmap(int k, int A, int B, int& sa, int& sb) {
    switch (k & 3) {
        case 0: sa = A;     sb = B;     break;
        case 1: sa = 2 - B; sb = A;     break;
        case 2: sa = 2 - A; sb = 2 - B; break;
        default: sa = B;    sb = 2 - A; break;
    }
}
__device__ __forceinline__ uint32_t smem_u32(const void* p) {
    uint32_t a;
    asm("{ .reg .u64 t; cvta.to.shared.u64 t, %1; cvt.u32.u64 %0, t; }"
        : "=r"(a) : "l"(p));
    return a;
}
__device__ __forceinline__ void mma_f16(float& c0, float& c1, float& c2, float& c3,
                                        uint32_t a0, uint32_t a1, uint32_t a2, uint32_t a3,
                                        uint32_t b0, uint32_t b1) {
    asm volatile(
        "mma.sync.aligned.m16n8k16.row.col.f32.f16.f16.f32 "
        "{%0,%1,%2,%3}, {%4,%5,%6,%7}, {%8,%9}, {%0,%1,%2,%3};"
        : "+f"(c0), "+f"(c1), "+f"(c2), "+f"(c3)
        : "r"(a0), "r"(a1), "r"(a2), "r"(a3), "r"(b0), "r"(b1));
}
__device__ __forceinline__ void ldmatrix_x4(uint32_t& r0, uint32_t& r1,
                                            uint32_t& r2, uint32_t& r3, uint32_t addr) {
    asm volatile("ldmatrix.sync.aligned.m8n8.x4.shared.b16 {%0,%1,%2,%3}, [%4];"
                 : "=r"(r0), "=r"(r1), "=r"(r2), "=r"(r3) : "r"(addr));
}

// ---------------------------------------------------------------------------
// x -> fp16 channel-last transpose: [b][ic][pix] f32 -> [b][pix][ic] f16
// ---------------------------------------------------------------------------
__global__ void cvt_x(const float* __restrict__ x)
{
    __shared__ float t[64][65];
    const int NPB = MAPH * MAPH;                 // 9216
    const int b = blockIdx.x / (NPB / 64);       // 144 tiles per batch
    const int pix0 = (blockIdx.x % (NPB / 64)) * 64;
    const float* src = x + (size_t)b * NCH * NPB;
    for (int i = threadIdx.x; i < 4096; i += 256) {
        int ic = i >> 6, px = i & 63;
        t[px][ic] = src[ic * NPB + pix0 + px];
    }
    __syncthreads();
    __half* dst = g_x16 + ((size_t)b * NPB + pix0) * NCH;
    for (int i = threadIdx.x; i < 4096; i += 256) {
        int px = i >> 6, ic = i & 63;
        dst[px * 64 + ic] = __float2half(t[px][ic]);
    }
}

// ---------------------------------------------------------------------------
// Weight prep: fold BN + rotation + (stage1) channel-roll perm; emit fp16
// B-fragment words for mma.m16n8k16:
//   word idx e = ((tap*4 + k16)*8 + nt)*64 + lane*2 + r
//   halves    = W[oc = nt*8 + lane/4][ic = k16*16 + 2*(lane%4) + 8r + {0,1}]
// ---------------------------------------------------------------------------
__global__ void prep_kernel(
    const float* __restrict__ dcn_w, const float* __restrict__ dcn_b,
    const float* __restrict__ c2w,   const float* __restrict__ c2b,
    const float* __restrict__ c3w,   const float* __restrict__ c3b,
    const float* __restrict__ gam,   const float* __restrict__ bet,
    const float* __restrict__ mu,    const float* __restrict__ va)
{
    int id = blockIdx.x * blockDim.x + threadIdx.x;
    const int W1N = 8 * WSETW, W2N = 4 * WSETW;

    if (id < W1N + 2 * W2N) {
        int setBase;
        uint32_t* dst;
        const float* src;
        int bnOff;
        if (id < W1N)            { dst = g_w1; src = dcn_w; bnOff = 0;   setBase = id; }
        else if (id < W1N + W2N) { dst = g_w2; src = c2w;   bnOff = 64;  setBase = id - W1N; }
        else                     { dst = g_w3; src = c3w;   bnOff = 128; setBase = id - W1N - W2N; }
        int set = setBase / WSETW;
        int e   = setBase % WSETW;
        int r    = e & 1;
        int lane = (e >> 1) & 31;
        int nt   = (e >> 6) & 7;
        int k16  = (e >> 9) & 3;
        int tap  = e >> 11;            // 0..8
        int g  = lane >> 2;
        int t4 = lane & 3;
        int oc  = nt * 8 + g;
        int ic0 = k16 * 16 + 2 * t4 + 8 * r;
        int sa, sb; rotmap(set & 3, tap / 3, tap % 3, sa, sb);
        float scale = gam[bnOff + oc] * rsqrtf(va[bnOff + oc] + 1e-5f);
        int sc0 = (bnOff == 0) ? ((ic0 + 8 * set) & 63) : ic0;
        int sc1 = (bnOff == 0) ? ((ic0 + 1 + 8 * set) & 63) : (ic0 + 1);
        float v0 = src[((oc * 64 + sc0) * 3 + sa) * 3 + sb] * scale;
        float v1 = src[((oc * 64 + sc1) * 3 + sa) * 3 + sb] * scale;
        uint32_t w = (uint32_t)__half_as_ushort(__float2half(v0))
                   | ((uint32_t)__half_as_ushort(__float2half(v1)) << 16);
        dst[setBase] = w;
        return;
    }
    id -= W1N + 2 * W2N;
    if (id < 192) {
        int s = id / 64, oc = id & 63;
        float scale = gam[s * 64 + oc] * rsqrtf(va[s * 64 + oc] + 1e-5f);
        const float* cb = (s == 0) ? dcn_b : ((s == 1) ? c2b : c3b);
        g_bias[id] = cb[oc] * scale + bet[s * 64 + oc] - mu[s * 64 + oc] * scale;
    }
}

// ---------------------------------------------------------------------------
// Conv kernel: fp16 mma.sync.m16n8k16 implicit GEMM, ldmatrix A feeds,
// channel-last fp16 activations everywhere.
// Block = 256 threads = 8 warps (warpM 0..3, warpN 0..1), 2 CTAs/SM.
// Pixel tile = 128 px (8 rows x 16 cols). Warp tile = 32 px x 32 oc.
// K = 576 as 9 taps x 4 k16-blocks.
// ---------------------------------------------------------------------------
template<int D, int STAGE>
__global__ void __launch_bounds__(256, 2)
conv_mma()
{
    constexpr int R = 8 + 2 * D;          // patch rows
    constexpr int C = 16 + 2 * D;         // patch cols
    constexpr int NPIX = R * C;

    extern __shared__ char sm[];
    uint32_t* sW    = (uint32_t*)sm;                       // 73728B
    __half*   sIn   = (__half*)(sm + 73728);               // NPIX * 144B
    float*    sBias = (float*)(sm + 73728 + NPIX * PIXB);  // 64
    float*    sRed  = sBias + 64;                          // 256 (stage 3)

    const int tid  = threadIdx.x;
    const int lane = tid & 31;
    const int wid  = tid >> 5;
    const int warpM = wid & 3;
    const int warpN = wid >> 2;

    const int br = blockIdx.z;
    const int b  = blockIdx.y;
    const int odd = br & 1;

    int pad, inValid, outH;
    if (STAGE == 1)      { pad = odd ? 5 : 1; inValid = 96;             outH = odd ? 104 : 96; }
    else if (STAGE == 2) { pad = odd ? 0 : 2; inValid = odd ? 104 : 96; outH = odd ? 100 : 96; }
    else                 { pad = odd ? 0 : 2; inValid = odd ? 100 : 96; outH = 96; }
    const int outW = outH;
    const int rowTiles = (outH + 7) >> 3;
    const int colTiles = (outW + 15) >> 4;
    const int rowTile = blockIdx.x;
    if (rowTile >= rowTiles) return;      // uniform per block

    const int srcStride = (STAGE == 1) ? MAPH : BSTR;
    const __half* inp = (STAGE == 1) ? (g_x16 + (size_t)b * MAPH * MAPH * NCH)
                       : (STAGE == 2) ? (g_buf1 + (size_t)(br * NBATCH + b) * BCHS * NCH)
                                      : (g_buf2 + (size_t)(br * NBATCH + b) * BCHS * NCH);
    __half* outp = ((STAGE == 1) ? g_buf1 : g_buf2)
                   + (size_t)(br * NBATCH + b) * BCHS * NCH;
    const uint32_t* wsrc = (STAGE == 1) ? (g_w1 + br * WSETW)
                          : (STAGE == 2) ? (g_w2 + (br & 3) * WSETW)
                                         : (g_w3 + (br & 3) * WSETW);

    // ---- stage weights (fragment words, linear copy) + bias ----
    {
        uint4* wd = (uint4*)sW;
        const uint4* ws = (const uint4*)wsrc;
        #pragma unroll 4
        for (int i = tid; i < WSETW / 4; i += 256) wd[i] = ws[i];
        if (tid < 64) sBias[tid] = g_bias[(STAGE - 1) * 64 + tid];
    }

    const int rowBase = rowTile * 8;
    const int g  = lane >> 2;
    const int t4 = lane & 3;

    // ldmatrix per-lane base: pixel col = lane&15, k-half-block = lane>>4
    const uint32_t sInU = smem_u32(sIn);
    const uint32_t aLane = sInU + ((warpM * 2) * C + (lane & 15)) * PIXB + (lane >> 4) * 16;

    uint4* sInV = (uint4*)sIn;
    const uint4* srcV = (const uint4*)inp;

    for (int ct = 0; ct < colTiles; ct++) {
        const int colBase = ct * 16;
        __syncthreads();   // prior-iter reads of sIn done before overwrite

        // ---- patch copy: vectorized channel-last (8 uint4 per pixel) ----
        for (int i = tid; i < NPIX * 8; i += 256) {
            int w   = i & 7;
            int pix = i >> 3;
            int r = pix / C;
            int c = pix - r * C;
            int gy = rowBase + r - pad;
            int gx = colBase + c - pad;
            uint4 v = make_uint4(0u, 0u, 0u, 0u);
            if ((unsigned)gy < (unsigned)inValid && (unsigned)gx < (unsigned)inValid)
                v = srcV[(size_t)(gy * srcStride + gx) * 8 + w];
            sInV[pix * 9 + w] = v;
        }
        __syncthreads();

        // ---- GEMM: 128px x 64oc x 576 ----
        float acc[2][4][4];
        #pragma unroll
        for (int mt = 0; mt < 2; mt++)
            #pragma unroll
            for (int nt = 0; nt < 4; nt++)
                #pragma unroll
                for (int q = 0; q < 4; q++) acc[mt][nt][q] = 0.f;

        #pragma unroll 1
        for (int tap = 0; tap < 9; tap++) {
            const int dy = (tap / 3) * D, dx = (tap % 3) * D;
            const uint32_t aT0 = aLane + (dy * C + dx) * PIXB;
            const uint32_t aT1 = aT0 + C * PIXB;
            const uint2* pB = (const uint2*)sW + ((tap * 4) * 8 + warpN * 4) * 32 + lane;

            #pragma unroll
            for (int k16 = 0; k16 < 4; k16++) {
                uint32_t a00, a01, a02, a03, a10, a11, a12, a13;
                ldmatrix_x4(a00, a01, a02, a03, aT0 + k16 * 32);
                ldmatrix_x4(a10, a11, a12, a13, aT1 + k16 * 32);
                const uint2* pBk = pB + k16 * 256;
                #pragma unroll
                for (int nt = 0; nt < 4; nt++) {
                    uint2 bb = pBk[nt * 32];
                    mma_f16(acc[0][nt][0], acc[0][nt][1], acc[0][nt][2], acc[0][nt][3],
                            a00, a01, a02, a03, bb.x, bb.y);
                    mma_f16(acc[1][nt][0], acc[1][nt][1], acc[1][nt][2], acc[1][nt][3],
                            a10, a11, a12, a13, bb.x, bb.y);
                }
            }
        }

        // ---- epilogue ----
        if (STAGE < 3) {
            #pragma unroll
            for (int mt = 0; mt < 2; mt++) {
                const int oy = rowBase + warpM * 2 + mt;
                const int ox0 = colBase + g;
                const int ox1 = ox0 + 8;
                if (oy < outH) {
                    #pragma unroll
                    for (int nt = 0; nt < 4; nt++) {
                        const int oc = warpN * 32 + nt * 8 + 2 * t4;
                        const float b0 = sBias[oc], b1 = sBias[oc + 1];
                        if (ox0 < outW) {
                            float2 f = make_float2(fmaxf(acc[mt][nt][0] + b0, 0.f),
                                                   fmaxf(acc[mt][nt][1] + b1, 0.f));
                            *(__half2*)(outp + (size_t)(oy * BSTR + ox0) * 64 + oc) =
                                __float22half2_rn(f);
                        }
                        if (ox1 < outW) {
                            float2 f = make_float2(fmaxf(acc[mt][nt][2] + b0, 0.f),
                                                   fmaxf(acc[mt][nt][3] + b1, 0.f));
                            *(__half2*)(outp + (size_t)(oy * BSTR + ox1) * 64 + oc) =
                                __float22half2_rn(f);
                        }
                    }
                }
            }
        } else {
            #pragma unroll
            for (int mt = 0; mt < 2; mt++) {
                float v0 = 0.f, v1 = 0.f;
                #pragma unroll
                for (int nt = 0; nt < 4; nt++) {
                    const int oc = warpN * 32 + nt * 8 + 2 * t4;
                    const float b0 = sBias[oc], b1 = sBias[oc + 1];
                    v0 = fmaxf(v0, fmaxf(acc[mt][nt][0] + b0, acc[mt][nt][1] + b1));
                    v1 = fmaxf(v1, fmaxf(acc[mt][nt][2] + b0, acc[mt][nt][3] + b1));
                }
                v0 = fmaxf(v0, __shfl_xor_sync(0xFFFFFFFF, v0, 1));
                v0 = fmaxf(v0, __shfl_xor_sync(0xFFFFFFFF, v0, 2));
                v1 = fmaxf(v1, __shfl_xor_sync(0xFFFFFFFF, v1, 1));
                v1 = fmaxf(v1, __shfl_xor_sync(0xFFFFFFFF, v1, 2));
                if (t4 == 0) {
                    const int px0 = warpM * 32 + mt * 16 + g;
                    sRed[px0 * 2 + warpN] = v0;
                    sRed[(px0 + 8) * 2 + warpN] = v1;
                }
            }
            __syncthreads();
            if (tid < 128) {
                const float m = fmaxf(sRed[tid * 2], sRed[tid * 2 + 1]);
                const int oy = rowBase + (tid >> 4);
                const int ox = colBase + (tid & 15);
                if (oy < MAPH && ox < MAPH)
                    g_bmax[((br * NBATCH + b) * MAPH + oy) * MAPH + ox] = m;
            }
        }
    }
}

// ---------------------------------------------------------------------------
// Cross-branch max + sigmoid + clip
// ---------------------------------------------------------------------------
__global__ void final_k(float* __restrict__ out)
{
    int i = blockIdx.x * blockDim.x + threadIdx.x;
    const int NPB = MAPH * MAPH;
    if (i >= NBATCH * NPB) return;
    int b = i / NPB, p = i - b * NPB;
    float m = g_bmax[b * NPB + p];
    #pragma unroll
    for (int br = 1; br < NBR; br++)
        m = fmaxf(m, g_bmax[(br * NBATCH + b) * NPB + p]);
    float s = 1.f / (1.f + expf(-m));
    out[i] = fminf(fmaxf(s, 0.0001f), 0.9999f);
}

// ---------------------------------------------------------------------------
// Launch
// ---------------------------------------------------------------------------
extern "C" void kernel_launch(void* const* d_in, const int* in_sizes, int n_in,
                              void* d_out, int out_size)
{
    const float* x     = (const float*)d_in[0];
    const float* dcn_w = (const float*)d_in[2];
    const float* dcn_b = (const float*)d_in[3];
    const float* c2w   = (const float*)d_in[4];
    const float* c2b   = (const float*)d_in[5];
    const float* c3w   = (const float*)d_in[6];
    const float* c3b   = (const float*)d_in[7];
    const float* gam   = (const float*)d_in[8];
    const float* bet   = (const float*)d_in[9];
    const float* mu    = (const float*)d_in[10];
    const float* va    = (const float*)d_in[11];

    constexpr int SMEM_D1 = 73728 + 10 * 18 * PIXB + 64 * 4 + 256 * 4;  // 100928
    constexpr int SMEM_D2 = 73728 + 12 * 20 * PIXB + 64 * 4 + 256 * 4;  // 109568

    cudaFuncSetAttribute((const void*)conv_mma<1, 1>,
                         cudaFuncAttributeMaxDynamicSharedMemorySize, SMEM_D1);
    cudaFuncSetAttribute((const void*)conv_mma<2, 2>,
                         cudaFuncAttributeMaxDynamicSharedMemorySize, SMEM_D2);
    cudaFuncSetAttribute((const void*)conv_mma<2, 3>,
                         cudaFuncAttributeMaxDynamicSharedMemorySize, SMEM_D2);

    cvt_x<<<NBATCH * (MAPH * MAPH / 64), 256>>>(x);

    const int prepN = 16 * WSETW + 192;
    prep_kernel<<<(prepN + 255) / 256, 256>>>(dcn_w, dcn_b, c2w, c2b, c3w, c3b,
                                              gam, bet, mu, va);

    // Stage 1 (D=1): even 96->96 (pad1), odd 96->104 (halo 5). max rowTiles = 13
    conv_mma<1, 1><<<dim3(13, NBATCH, NBR), 256, SMEM_D1>>>();
    // Stage 2 (D=2): even 96->96 (pad2), odd 104->100 (valid). max rowTiles = 13
    conv_mma<2, 2><<<dim3(13, NBATCH, NBR), 256, SMEM_D2>>>();
    // Stage 3 (D=2) + channel max: even 96->96, odd 100->96. rowTiles = 12
    conv_mma<2, 3><<<dim3(12, NBATCH, NBR), 256, SMEM_D2>>>();

    final_k<<<(NBATCH * MAPH * MAPH + 255) / 256, 256>>>((float*)d_out);
}